// round 13
// baseline (speedup 1.0000x reference)
#include <cuda_runtime.h>
#include <cuda_fp16.h>
#include <math.h>
#include <cstdint>

#define N 1024
#define E 128
#define NEG 0.2f

#define I_PER_CTA 8
#define BMJ 128
#define LDH 136                   // half stride (272 B rows)
#define TILE_B (BMJ * LDH * 2)    // 34816
#define OFF_A0 0
#define OFF_A1 34816
#define OFF_B  69632
#define OFF_RS 104448             // rsum: 128 x 2 floats
#define SMEM_DYN (OFF_RS + 1024)

// ---- scratch ----
__device__ float g_base[N * E];
__device__ float g_s[N];
__device__ float g_wa2[E];
__device__ float g_logits[(size_t)N * N];
__device__ __half g_Bh[E * E];   // pc_Wp fp16, [k][n]

__device__ __forceinline__ float lrelu(float x) { return fmaxf(x, NEG * x); }

__device__ __forceinline__ uint32_t smem_u32(const void* p) {
    return (uint32_t)__cvta_generic_to_shared(p);
}
__device__ __forceinline__ void ldsm_x4(uint32_t* r, uint32_t addr) {
    asm volatile("ldmatrix.sync.aligned.m8n8.x4.shared.b16 {%0,%1,%2,%3}, [%4];"
                 : "=r"(r[0]), "=r"(r[1]), "=r"(r[2]), "=r"(r[3]) : "r"(addr));
}
__device__ __forceinline__ void ldsm_x4_t(uint32_t* r, uint32_t addr) {
    asm volatile("ldmatrix.sync.aligned.m8n8.x4.trans.shared.b16 {%0,%1,%2,%3}, [%4];"
                 : "=r"(r[0]), "=r"(r[1]), "=r"(r[2]), "=r"(r[3]) : "r"(addr));
}
// fp16-acc mma: D(16x8 fp16) += A(16x16) * B(16x8)
__device__ __forceinline__ void mma_h(uint32_t& d0, uint32_t& d1,
                                      const uint32_t* a, uint32_t b0, uint32_t b1) {
    asm volatile("mma.sync.aligned.m16n8k16.row.col.f16.f16.f16.f16 "
                 "{%0,%1},{%2,%3,%4,%5},{%6,%7},{%0,%1};"
                 : "+r"(d0), "+r"(d1)
                 : "r"(a[0]), "r"(a[1]), "r"(a[2]), "r"(a[3]), "r"(b0), "r"(b1));
}
// fp32-acc mma for the reduction
__device__ __forceinline__ void mma_hf(float* d, const uint32_t* a, uint32_t b0, uint32_t b1) {
    asm volatile("mma.sync.aligned.m16n8k16.row.col.f32.f16.f16.f32 "
                 "{%0,%1,%2,%3},{%4,%5,%6,%7},{%8,%9},{%0,%1,%2,%3};"
                 : "+f"(d[0]), "+f"(d[1]), "+f"(d[2]), "+f"(d[3])
                 : "r"(a[0]), "r"(a[1]), "r"(a[2]), "r"(a[3]), "r"(b0), "r"(b1));
}
__device__ __forceinline__ uint32_t h2bits(__half2 v) { return *(uint32_t*)&v; }

// ---------------- precompute ----------------
__global__ void k_pre(const float* __restrict__ embs, const float* __restrict__ W,
                      const float* __restrict__ pcW, const float* __restrict__ pcb,
                      const float* __restrict__ aW) {
    __shared__ float es[E];
    __shared__ float ws[E];
    __shared__ float red[E];
    int i = blockIdx.x, l = threadIdx.x;
    es[l] = embs[i * E + l];
    __syncthreads();
    float acc = 0.f;
#pragma unroll 8
    for (int k = 0; k < E; k++) acc = fmaf(es[k], W[k * E + l], acc);
    ws[l] = acc;
    red[l] = acc * aW[l];
    __syncthreads();
    float b = pcb[l];
#pragma unroll 8
    for (int k = 0; k < E; k++) b = fmaf(ws[k], pcW[k * E + l], b);
    g_base[i * E + l] = b;
    for (int off = 64; off > 0; off >>= 1) {
        __syncthreads();
        if (l < off) red[l] += red[l + off];
    }
    __syncthreads();
    if (l == 0) g_s[i] = red[0];
}

__global__ void k_wa2(const float* __restrict__ W, const float* __restrict__ aW) {
    __shared__ float a2s[E];
    int m = threadIdx.x;
    a2s[m] = aW[E + m];
    __syncthreads();
    float acc = 0.f;
#pragma unroll 8
    for (int k = 0; k < E; k++) acc = fmaf(W[m * E + k], a2s[k], acc);
    g_wa2[m] = acc;
}

__global__ void k_bh(const float* __restrict__ pcW) {
    int idx = blockIdx.x * 128 + threadIdx.x;
    g_Bh[idx] = __float2half(pcW[E * E + idx]);
}

// ---------------- big kernel: raw mma, 2 CTAs/SM ----------------
// grid (8, 128): blockIdx.x = 128-row j-block, blockIdx.y = 8-i chunk.
__global__ void __launch_bounds__(256, 2)
k_big(const float* __restrict__ pde, const int* __restrict__ adj,
      const float* __restrict__ ab_ptr) {
    extern __shared__ char sm[];
    const uint32_t sb = smem_u32(sm);
    float* rsum = (float*)(sm + OFF_RS);

    const int tid = threadIdx.x;
    const int lane = tid & 31;
    const int wid = tid >> 5;
    const int grp = lane >> 2, tig = lane & 3;
    const int lrow = lane & 15, lcb = (lane >> 4) * 8;
    const int j0 = blockIdx.x * BMJ;
    const int i_base = blockIdx.y * I_PER_CTA;
    const float ab = ab_ptr[0];
    const __half2 slope = __float2half2_rn(NEG);

    const int wr = (wid & 3) * 32;     // warp row base
    const int wcg = wid >> 2;          // col group 0/1
    const int wc = wcg * 64;           // warp col base

    // ---- prologue 1: base -> fp16 into A0 region ----
#pragma unroll
    for (int t = 0; t < 8; t++) {
        int idx = tid + t * 256;
        int row = idx >> 4, c8 = (idx & 15) * 8;
        const float4* g = (const float4*)(g_base + (size_t)(j0 + row) * E + c8);
        float4 v0 = g[0], v1 = g[1];
        __half2 p0 = __floats2half2_rn(v0.x, v0.y);
        __half2 p1 = __floats2half2_rn(v0.z, v0.w);
        __half2 p2 = __floats2half2_rn(v1.x, v1.y);
        __half2 p3 = __floats2half2_rn(v1.z, v1.w);
        uint4 o;
        o.x = h2bits(p0); o.y = h2bits(p1); o.z = h2bits(p2); o.w = h2bits(p3);
        *(uint4*)(sm + OFF_A0 + (row * LDH + c8) * 2) = o;
    }
    __syncthreads();

    // bfrag: 2 row-blocks x 8 col-blocks, c0/c1 regs each (layout == mma fp16 acc)
    uint32_t bf0[2][8], bf1[2][8];
#pragma unroll
    for (int rb = 0; rb < 2; rb++)
#pragma unroll
        for (int q = 0; q < 4; q++) {
            uint32_t r[4];
            ldsm_x4(r, sb + OFF_A0 + ((wr + 16 * rb + lrow) * LDH + wc + 16 * q + lcb) * 2);
            bf0[rb][2 * q] = r[0]; bf1[rb][2 * q] = r[1];
            bf0[rb][2 * q + 1] = r[2]; bf1[rb][2 * q + 1] = r[3];
        }
    // w2 operand regs: B[k][0] = wa2, else 0 -> only grp==0 lanes nonzero
    uint32_t w2lo[4], w2hi[4];
#pragma unroll
    for (int kb = 0; kb < 4; kb++) {
        if (grp == 0) {
            int k0 = wc + 16 * kb + 2 * tig;
            w2lo[kb] = h2bits(__floats2half2_rn(g_wa2[k0], g_wa2[k0 + 1]));
            w2hi[kb] = h2bits(__floats2half2_rn(g_wa2[k0 + 8], g_wa2[k0 + 9]));
        } else { w2lo[kb] = 0; w2hi[kb] = 0; }
    }
    __syncthreads();   // all bfrag reads of A0 done before overwrite

    // ---- prologue 2: B tile + A tile 0 ----
#pragma unroll
    for (int t = 0; t < 8; t++) {
        int idx = tid + t * 256;
        int row = idx >> 4, c8 = (idx & 15) * 8;
        *(uint4*)(sm + OFF_B + (row * LDH + c8) * 2) = *(const uint4*)(g_Bh + row * E + c8);
    }
    {
        const float* gA = pde + ((size_t)i_base * N + j0) * E;
#pragma unroll
        for (int t = 0; t < 8; t++) {
            int idx = tid + t * 256;
            int row = idx >> 4, c8 = (idx & 15) * 8;
            const float4* g = (const float4*)(gA + (size_t)row * E + c8);
            float4 v0 = g[0], v1 = g[1];
            __half2 p0 = __floats2half2_rn(v0.x, v0.y);
            __half2 p1 = __floats2half2_rn(v0.z, v0.w);
            __half2 p2 = __floats2half2_rn(v1.x, v1.y);
            __half2 p3 = __floats2half2_rn(v1.z, v1.w);
            uint4 o;
            o.x = h2bits(p0); o.y = h2bits(p1); o.z = h2bits(p2); o.w = h2bits(p3);
            *(uint4*)(sm + OFF_A0 + (row * LDH + c8) * 2) = o;
        }
    }
    __syncthreads();

    const uint32_t bB = sb + OFF_B;

    for (int s = 0; s < I_PER_CTA; s++) {
        const uint32_t bA = sb + ((s & 1) ? OFF_A1 : OFF_A0);
        const int i = i_base + s;

        // ---- main mma: 128x128x128, fp16 acc, warp tile 32x64 ----
        uint32_t fc0[2][8], fc1[2][8];
#pragma unroll
        for (int rb = 0; rb < 2; rb++)
#pragma unroll
            for (int cb = 0; cb < 8; cb++) { fc0[rb][cb] = 0; fc1[rb][cb] = 0; }

#pragma unroll
        for (int ks = 0; ks < 8; ks++) {
            uint32_t a[2][4];
            ldsm_x4(a[0], bA + ((wr + lrow) * LDH + ks * 16 + lcb) * 2);
            ldsm_x4(a[1], bA + ((wr + 16 + lrow) * LDH + ks * 16 + lcb) * 2);
#pragma unroll
            for (int q = 0; q < 4; q++) {
                uint32_t b[4];
                ldsm_x4_t(b, bB + ((ks * 16 + lrow) * LDH + wc + 16 * q + lcb) * 2);
#pragma unroll
                for (int rb = 0; rb < 2; rb++) {
                    mma_h(fc0[rb][2 * q], fc1[rb][2 * q], a[rb], b[0], b[1]);
                    mma_h(fc0[rb][2 * q + 1], fc1[rb][2 * q + 1], a[rb], b[2], b[3]);
                }
            }
        }

        // ---- P = lrelu(fc + base), in registers ----
#pragma unroll
        for (int rb = 0; rb < 2; rb++)
#pragma unroll
            for (int cb = 0; cb < 8; cb++) {
                __half2 v0 = __hadd2(*(__half2*)&fc0[rb][cb], *(__half2*)&bf0[rb][cb]);
                __half2 v1 = __hadd2(*(__half2*)&fc1[rb][cb], *(__half2*)&bf1[rb][cb]);
                *(__half2*)&fc0[rb][cb] = __hmax2(v0, __hmul2(v0, slope));
                *(__half2*)&fc1[rb][cb] = __hmax2(v1, __hmul2(v1, slope));
            }

        // ---- reduction mma: rowsum = P(32x64) @ w2(64x8, col0=wa2) ----
        float racc[2][4];
#pragma unroll
        for (int rb = 0; rb < 2; rb++) {
#pragma unroll
            for (int e = 0; e < 4; e++) racc[rb][e] = 0.f;
#pragma unroll
            for (int kb = 0; kb < 4; kb++) {
                uint32_t aop[4] = { fc0[rb][2 * kb], fc1[rb][2 * kb],
                                    fc0[rb][2 * kb + 1], fc1[rb][2 * kb + 1] };
                mma_hf(racc[rb], aop, w2lo[kb], w2hi[kb]);
            }
            if (tig == 0) {
                rsum[(wr + 16 * rb + grp) * 2 + wcg] = racc[rb][0];
                rsum[(wr + 16 * rb + 8 + grp) * 2 + wcg] = racc[rb][2];
            }
        }
        __syncthreads();   // rsum visible; all mma reads of A[s] done

        // ---- finalize logits ----
        if (tid < 128) {
            float part = rsum[2 * tid] + rsum[2 * tid + 1];
            float lg = lrelu(g_s[i] + part + ab);
            size_t oidx = (size_t)i * N + j0 + tid;
            g_logits[oidx] = (adj[oidx] == 1) ? lg : -1e30f;
        }

        // ---- copy next A tile (other CTA on this SM hides the latency) ----
        if (s + 1 < I_PER_CTA) {
            const float* gA = pde + ((size_t)(i_base + s + 1) * N + j0) * E;
            char* dst = sm + ((s & 1) ? OFF_A0 : OFF_A1);
#pragma unroll
            for (int t = 0; t < 8; t++) {
                int idx = tid + t * 256;
                int row = idx >> 4, c8 = (idx & 15) * 8;
                const float4* g = (const float4*)(gA + (size_t)row * E + c8);
                float4 v0 = g[0], v1 = g[1];
                __half2 p0 = __floats2half2_rn(v0.x, v0.y);
                __half2 p1 = __floats2half2_rn(v0.z, v0.w);
                __half2 p2 = __floats2half2_rn(v1.x, v1.y);
                __half2 p3 = __floats2half2_rn(v1.z, v1.w);
                uint4 o;
                o.x = h2bits(p0); o.y = h2bits(p1); o.z = h2bits(p2); o.w = h2bits(p3);
                *(uint4*)(dst + (row * LDH + c8) * 2) = o;
            }
        }
        __syncthreads();   // A[s+1] ready; rsum reads done
    }
}

// ---------------- softmax + attn@embs + concat ----------------
#define RPB 8
__global__ void __launch_bounds__(256)
k_out(const float* __restrict__ embs, float* __restrict__ out) {
    __shared__ float attn[RPB][N];
    __shared__ float red[256];
    __shared__ float partial[RPB][E];
    const int i0 = blockIdx.x * RPB;
    const int t = threadIdx.x;

    float inv[RPB];
#pragma unroll
    for (int r = 0; r < RPB; r++) {
        const float* lg = g_logits + (size_t)(i0 + r) * N;
        float m = -1e30f;
#pragma unroll
        for (int q = 0; q < N / 256; q++) m = fmaxf(m, lg[t + q * 256]);
        red[t] = m;
        for (int off = 128; off > 0; off >>= 1) {
            __syncthreads();
            if (t < off) red[t] = fmaxf(red[t], red[t + off]);
        }
        __syncthreads();
        m = red[0];
        __syncthreads();
        float s = 0.f;
#pragma unroll
        for (int q = 0; q < N / 256; q++) {
            float e = expf(lg[t + q * 256] - m);
            attn[r][t + q * 256] = e;
            s += e;
        }
        red[t] = s;
        for (int off = 128; off > 0; off >>= 1) {
            __syncthreads();
            if (t < off) red[t] += red[t + off];
        }
        __syncthreads();
        inv[r] = 1.f / red[0];
        __syncthreads();
    }

    const int col = t & 127, h = t >> 7;
    float acc[RPB];
#pragma unroll
    for (int r = 0; r < RPB; r++) acc[r] = 0.f;
    const int jb = h * 512;
#pragma unroll 8
    for (int j = jb; j < jb + 512; j++) {
        float ev = embs[j * E + col];
#pragma unroll
        for (int r = 0; r < RPB; r++) acc[r] = fmaf(attn[r][j], ev, acc[r]);
    }
    if (h == 1) {
#pragma unroll
        for (int r = 0; r < RPB; r++) partial[r][col] = acc[r];
    }
    __syncthreads();
    if (h == 0) {
#pragma unroll
        for (int r = 0; r < RPB; r++) {
            int i = i0 + r;
            out[(size_t)i * (2 * E) + col] = embs[i * E + col];
            out[(size_t)i * (2 * E) + E + col] = (acc[r] + partial[r][col]) * inv[r];
        }
    }
}

// ---------------- launch ----------------
extern "C" void kernel_launch(void* const* d_in, const int* in_sizes, int n_in,
                              void* d_out, int out_size) {
    const float* embs = (const float*)d_in[0];
    const int*   adj  = (const int*)d_in[1];
    const float* pde  = (const float*)d_in[2];
    const float* W    = (const float*)d_in[3];
    const float* pcW  = (const float*)d_in[4];
    const float* pcb  = (const float*)d_in[5];
    const float* aW   = (const float*)d_in[6];
    const float* ab   = (const float*)d_in[7];
    float* out = (float*)d_out;

    cudaFuncSetAttribute(k_big, cudaFuncAttributeMaxDynamicSharedMemorySize,
                         (int)SMEM_DYN);

    k_pre<<<N, E>>>(embs, W, pcW, pcb, aW);                       // launch 0
    k_wa2<<<1, E>>>(W, aW);                                       // launch 1
    k_bh<<<E, E>>>(pcW);                                          // launch 2
    k_big<<<dim3(N / BMJ, N / I_PER_CTA), 256, SMEM_DYN>>>(pde, adj, ab);  // launch 3
    k_out<<<N / RPB, 256>>>(embs, out);                           // launch 4
}

// round 14
// speedup vs baseline: 1.2921x; 1.2921x over previous
#include <cuda_runtime.h>
#include <cuda_fp16.h>
#include <math.h>
#include <cstdint>

#define N 1024
#define E 128
#define NEG 0.2f

#define I_PER_CTA 8
#define BMJ 128
#define LDH 136                   // half stride (272 B rows)
#define TILE_B (BMJ * LDH * 2)    // 34816
#define OFF_A0 0
#define OFF_A1 34816
#define OFF_B  69632
#define OFF_RS 104448             // rsum: 128 x 2 floats
#define SMEM_DYN (OFF_RS + 1024)

// ---- scratch ----
__device__ float g_base[N * E];
__device__ float g_s[N];
__device__ float g_wa2[E];
__device__ float g_logits[(size_t)N * N];
__device__ __half g_Bh[E * E];   // pc_Wp fp16, [k][n]

__device__ __forceinline__ float lrelu(float x) { return fmaxf(x, NEG * x); }

__device__ __forceinline__ uint32_t smem_u32(const void* p) {
    return (uint32_t)__cvta_generic_to_shared(p);
}
__device__ __forceinline__ void ldsm_x4(uint32_t* r, uint32_t addr) {
    asm volatile("ldmatrix.sync.aligned.m8n8.x4.shared.b16 {%0,%1,%2,%3}, [%4];"
                 : "=r"(r[0]), "=r"(r[1]), "=r"(r[2]), "=r"(r[3]) : "r"(addr));
}
__device__ __forceinline__ void ldsm_x4_t(uint32_t* r, uint32_t addr) {
    asm volatile("ldmatrix.sync.aligned.m8n8.x4.trans.shared.b16 {%0,%1,%2,%3}, [%4];"
                 : "=r"(r[0]), "=r"(r[1]), "=r"(r[2]), "=r"(r[3]) : "r"(addr));
}
__device__ __forceinline__ void mma_h(uint32_t& d0, uint32_t& d1,
                                      const uint32_t* a, uint32_t b0, uint32_t b1) {
    asm volatile("mma.sync.aligned.m16n8k16.row.col.f16.f16.f16.f16 "
                 "{%0,%1},{%2,%3,%4,%5},{%6,%7},{%0,%1};"
                 : "+r"(d0), "+r"(d1)
                 : "r"(a[0]), "r"(a[1]), "r"(a[2]), "r"(a[3]), "r"(b0), "r"(b1));
}
__device__ __forceinline__ void mma_hf(float* d, const uint32_t* a, uint32_t b0, uint32_t b1) {
    asm volatile("mma.sync.aligned.m16n8k16.row.col.f32.f16.f16.f32 "
                 "{%0,%1,%2,%3},{%4,%5,%6,%7},{%8,%9},{%0,%1,%2,%3};"
                 : "+f"(d[0]), "+f"(d[1]), "+f"(d[2]), "+f"(d[3])
                 : "r"(a[0]), "r"(a[1]), "r"(a[2]), "r"(a[3]), "r"(b0), "r"(b1));
}
__device__ __forceinline__ uint32_t h2bits(__half2 v) { return *(uint32_t*)&v; }

// ---------------- k_pre: 8 rows/block, W/pcW staged through smem ----------------
#define IB 8
#define PRE_SMEM ((16384 + 2 * IB * 128 + 64) * 4)
__global__ void __launch_bounds__(128)
k_pre(const float* __restrict__ embs, const float* __restrict__ W,
      const float* __restrict__ pcW, const float* __restrict__ pcb,
      const float* __restrict__ aW) {
    extern __shared__ float ps[];
    float* Wsm = ps;                    // 16384 floats
    float* es = ps + 16384;             // IB*128
    float* ws = es + IB * 128;          // IB*128
    float* scr = ws + IB * 128;         // 64
    const int l = threadIdx.x;
    const int warp = l >> 5, lane = l & 31;
    const int i0 = blockIdx.x * IB;

    // load W into smem (4096 float4 by 128 threads)
#pragma unroll
    for (int t = 0; t < 32; t++)
        ((float4*)Wsm)[l + t * 128] = ((const float4*)W)[l + t * 128];
#pragma unroll
    for (int r = 0; r < IB; r++) es[r * 128 + l] = embs[(i0 + r) * 128 + l];
    __syncthreads();

    // wf[r][l] = sum_k es[r][k] * W[k][l]
    float acc[IB];
#pragma unroll
    for (int r = 0; r < IB; r++) acc[r] = 0.f;
    for (int k = 0; k < 128; k++) {
        float wv = Wsm[k * 128 + l];
#pragma unroll
        for (int r = 0; r < IB; r++) acc[r] = fmaf(es[r * 128 + k], wv, acc[r]);
    }
#pragma unroll
    for (int r = 0; r < IB; r++) ws[r * 128 + l] = acc[r];

    // s[i0+r] = sum_l wf[r][l] * aW[l]
    float a1 = aW[l];
#pragma unroll
    for (int r = 0; r < IB; r++) {
        float v = acc[r] * a1;
#pragma unroll
        for (int off = 16; off > 0; off >>= 1) v += __shfl_xor_sync(0xffffffffu, v, off);
        if (lane == 0) scr[r * 4 + warp] = v;
    }
    __syncthreads();
    if (l < IB)
        g_s[i0 + l] = scr[l * 4] + scr[l * 4 + 1] + scr[l * 4 + 2] + scr[l * 4 + 3];
    __syncthreads();

    // overwrite Wsm with pcW (top half, the pc_Wc part)
#pragma unroll
    for (int t = 0; t < 32; t++)
        ((float4*)Wsm)[l + t * 128] = ((const float4*)pcW)[l + t * 128];
    __syncthreads();

    // base[r][l] = pcb[l] + sum_k wf[r][k] * pcW[k][l]
    float b[IB];
    float bias = pcb[l];
#pragma unroll
    for (int r = 0; r < IB; r++) b[r] = bias;
    for (int k = 0; k < 128; k++) {
        float wv = Wsm[k * 128 + l];
#pragma unroll
        for (int r = 0; r < IB; r++) b[r] = fmaf(ws[r * 128 + k], wv, b[r]);
    }
#pragma unroll
    for (int r = 0; r < IB; r++) g_base[(size_t)(i0 + r) * 128 + l] = b[r];
}

__global__ void k_wa2(const float* __restrict__ W, const float* __restrict__ aW) {
    __shared__ float a2s[E];
    int m = threadIdx.x;
    a2s[m] = aW[E + m];
    __syncthreads();
    float acc = 0.f;
#pragma unroll 8
    for (int k = 0; k < E; k++) acc = fmaf(W[m * E + k], a2s[k], acc);
    g_wa2[m] = acc;
}

__global__ void k_bh(const float* __restrict__ pcW) {
    int idx = blockIdx.x * 128 + threadIdx.x;
    g_Bh[idx] = __float2half(pcW[E * E + idx]);
}

// ---------------- big kernel: raw mma, 2 CTAs/SM, copy-first ordering ----------------
__global__ void __launch_bounds__(256, 2)
k_big(const float* __restrict__ pde, const int* __restrict__ adj,
      const float* __restrict__ ab_ptr) {
    extern __shared__ char sm[];
    const uint32_t sb = smem_u32(sm);
    float* rsum = (float*)(sm + OFF_RS);

    const int tid = threadIdx.x;
    const int lane = tid & 31;
    const int wid = tid >> 5;
    const int grp = lane >> 2, tig = lane & 3;
    const int lrow = lane & 15, lcb = (lane >> 4) * 8;
    const int j0 = blockIdx.x * BMJ;
    const int i_base = blockIdx.y * I_PER_CTA;
    const float ab = ab_ptr[0];
    const __half2 slope = __float2half2_rn(NEG);

    const int wr = (wid & 3) * 32;
    const int wcg = wid >> 2;
    const int wc = wcg * 64;

    // ---- prologue 1: base -> fp16 into A0 region ----
#pragma unroll
    for (int t = 0; t < 8; t++) {
        int idx = tid + t * 256;
        int row = idx >> 4, c8 = (idx & 15) * 8;
        const float4* g = (const float4*)(g_base + (size_t)(j0 + row) * E + c8);
        float4 v0 = g[0], v1 = g[1];
        __half2 p0 = __floats2half2_rn(v0.x, v0.y);
        __half2 p1 = __floats2half2_rn(v0.z, v0.w);
        __half2 p2 = __floats2half2_rn(v1.x, v1.y);
        __half2 p3 = __floats2half2_rn(v1.z, v1.w);
        uint4 o;
        o.x = h2bits(p0); o.y = h2bits(p1); o.z = h2bits(p2); o.w = h2bits(p3);
        *(uint4*)(sm + OFF_A0 + (row * LDH + c8) * 2) = o;
    }
    __syncthreads();

    uint32_t bf0[2][8], bf1[2][8];
#pragma unroll
    for (int rb = 0; rb < 2; rb++)
#pragma unroll
        for (int q = 0; q < 4; q++) {
            uint32_t r[4];
            ldsm_x4(r, sb + OFF_A0 + ((wr + 16 * rb + lrow) * LDH + wc + 16 * q + lcb) * 2);
            bf0[rb][2 * q] = r[0]; bf1[rb][2 * q] = r[1];
            bf0[rb][2 * q + 1] = r[2]; bf1[rb][2 * q + 1] = r[3];
        }
    uint32_t w2lo[4], w2hi[4];
#pragma unroll
    for (int kb = 0; kb < 4; kb++) {
        if (grp == 0) {
            int k0 = wc + 16 * kb + 2 * tig;
            w2lo[kb] = h2bits(__floats2half2_rn(g_wa2[k0], g_wa2[k0 + 1]));
            w2hi[kb] = h2bits(__floats2half2_rn(g_wa2[k0 + 8], g_wa2[k0 + 9]));
        } else { w2lo[kb] = 0; w2hi[kb] = 0; }
    }
    __syncthreads();

    // ---- prologue 2: B tile + A tile 0 ----
#pragma unroll
    for (int t = 0; t < 8; t++) {
        int idx = tid + t * 256;
        int row = idx >> 4, c8 = (idx & 15) * 8;
        *(uint4*)(sm + OFF_B + (row * LDH + c8) * 2) = *(const uint4*)(g_Bh + row * E + c8);
    }
    {
        const float* gA = pde + ((size_t)i_base * N + j0) * E;
#pragma unroll
        for (int t = 0; t < 8; t++) {
            int idx = tid + t * 256;
            int row = idx >> 4, c8 = (idx & 15) * 8;
            const float4* g = (const float4*)(gA + (size_t)row * E + c8);
            float4 v0 = g[0], v1 = g[1];
            __half2 p0 = __floats2half2_rn(v0.x, v0.y);
            __half2 p1 = __floats2half2_rn(v0.z, v0.w);
            __half2 p2 = __floats2half2_rn(v1.x, v1.y);
            __half2 p3 = __floats2half2_rn(v1.z, v1.w);
            uint4 o;
            o.x = h2bits(p0); o.y = h2bits(p1); o.z = h2bits(p2); o.w = h2bits(p3);
            *(uint4*)(sm + OFF_A0 + (row * LDH + c8) * 2) = o;
        }
    }
    __syncthreads();

    const uint32_t bB = sb + OFF_B;

    for (int s = 0; s < I_PER_CTA; s++) {
        const uint32_t bA = sb + ((s & 1) ? OFF_A1 : OFF_A0);
        const int i = i_base + s;

        // ---- copy NEXT A tile first: DRAM latency hides behind the mma below ----
        if (s + 1 < I_PER_CTA) {
            const float* gA = pde + ((size_t)(i_base + s + 1) * N + j0) * E;
            char* dst = sm + ((s & 1) ? OFF_A0 : OFF_A1);
#pragma unroll
            for (int t = 0; t < 8; t++) {
                int idx = tid + t * 256;
                int row = idx >> 4, c8 = (idx & 15) * 8;
                const float4* g = (const float4*)(gA + (size_t)row * E + c8);
                float4 v0 = g[0], v1 = g[1];
                __half2 p0 = __floats2half2_rn(v0.x, v0.y);
                __half2 p1 = __floats2half2_rn(v0.z, v0.w);
                __half2 p2 = __floats2half2_rn(v1.x, v1.y);
                __half2 p3 = __floats2half2_rn(v1.z, v1.w);
                uint4 o;
                o.x = h2bits(p0); o.y = h2bits(p1); o.z = h2bits(p2); o.w = h2bits(p3);
                *(uint4*)(dst + (row * LDH + c8) * 2) = o;
            }
        }

        // ---- main mma: 128x128x128, fp16 acc, warp tile 32x64 ----
        uint32_t fc0[2][8], fc1[2][8];
#pragma unroll
        for (int rb = 0; rb < 2; rb++)
#pragma unroll
            for (int cb = 0; cb < 8; cb++) { fc0[rb][cb] = 0; fc1[rb][cb] = 0; }

#pragma unroll
        for (int ks = 0; ks < 8; ks++) {
            uint32_t a[2][4];
            ldsm_x4(a[0], bA + ((wr + lrow) * LDH + ks * 16 + lcb) * 2);
            ldsm_x4(a[1], bA + ((wr + 16 + lrow) * LDH + ks * 16 + lcb) * 2);
#pragma unroll
            for (int q = 0; q < 4; q++) {
                uint32_t b[4];
                ldsm_x4_t(b, bB + ((ks * 16 + lrow) * LDH + wc + 16 * q + lcb) * 2);
#pragma unroll
                for (int rb = 0; rb < 2; rb++) {
                    mma_h(fc0[rb][2 * q], fc1[rb][2 * q], a[rb], b[0], b[1]);
                    mma_h(fc0[rb][2 * q + 1], fc1[rb][2 * q + 1], a[rb], b[2], b[3]);
                }
            }
        }

        // ---- P = lrelu(fc + base), in registers ----
#pragma unroll
        for (int rb = 0; rb < 2; rb++)
#pragma unroll
            for (int cb = 0; cb < 8; cb++) {
                __half2 v0 = __hadd2(*(__half2*)&fc0[rb][cb], *(__half2*)&bf0[rb][cb]);
                __half2 v1 = __hadd2(*(__half2*)&fc1[rb][cb], *(__half2*)&bf1[rb][cb]);
                *(__half2*)&fc0[rb][cb] = __hmax2(v0, __hmul2(v0, slope));
                *(__half2*)&fc1[rb][cb] = __hmax2(v1, __hmul2(v1, slope));
            }

        // ---- reduction mma ----
        float racc[2][4];
#pragma unroll
        for (int rb = 0; rb < 2; rb++) {
#pragma unroll
            for (int e = 0; e < 4; e++) racc[rb][e] = 0.f;
#pragma unroll
            for (int kb = 0; kb < 4; kb++) {
                uint32_t aop[4] = { fc0[rb][2 * kb], fc1[rb][2 * kb],
                                    fc0[rb][2 * kb + 1], fc1[rb][2 * kb + 1] };
                mma_hf(racc[rb], aop, w2lo[kb], w2hi[kb]);
            }
            if (tig == 0) {
                rsum[(wr + 16 * rb + grp) * 2 + wcg] = racc[rb][0];
                rsum[(wr + 16 * rb + 8 + grp) * 2 + wcg] = racc[rb][2];
            }
        }
        __syncthreads();   // rsum visible; A[s] reads done; A[s+1] stores done

        if (tid < 128) {
            float part = rsum[2 * tid] + rsum[2 * tid + 1];
            float lg = lrelu(g_s[i] + part + ab);
            size_t oidx = (size_t)i * N + j0 + tid;
            g_logits[oidx] = (adj[oidx] == 1) ? lg : -1e30f;
        }
        __syncthreads();   // rsum reads done before next tile's writes
    }
}

// ---------------- softmax + attn@embs + concat (shuffle reductions) ----------------
#define RPB 8
__global__ void __launch_bounds__(256)
k_out(const float* __restrict__ embs, float* __restrict__ out) {
    __shared__ float attn[RPB][N];
    __shared__ float red16[16];
    __shared__ float partial[RPB][E];
    const int i0 = blockIdx.x * RPB;
    const int t = threadIdx.x;
    const int warp = t >> 5, lane = t & 31;

    float inv[RPB];
#pragma unroll
    for (int r = 0; r < RPB; r++) {
        const float* lg = g_logits + (size_t)(i0 + r) * N;
        float v0 = lg[t], v1 = lg[t + 256], v2 = lg[t + 512], v3 = lg[t + 768];
        float m = fmaxf(fmaxf(v0, v1), fmaxf(v2, v3));
#pragma unroll
        for (int off = 16; off > 0; off >>= 1)
            m = fmaxf(m, __shfl_xor_sync(0xffffffffu, m, off));
        if (lane == 0) red16[warp] = m;
        __syncthreads();
        m = red16[0];
#pragma unroll
        for (int w = 1; w < 8; w++) m = fmaxf(m, red16[w]);

        float e0 = expf(v0 - m), e1 = expf(v1 - m), e2 = expf(v2 - m), e3 = expf(v3 - m);
        attn[r][t] = e0; attn[r][t + 256] = e1; attn[r][t + 512] = e2; attn[r][t + 768] = e3;
        float s = e0 + e1 + e2 + e3;
#pragma unroll
        for (int off = 16; off > 0; off >>= 1)
            s += __shfl_xor_sync(0xffffffffu, s, off);
        if (lane == 0) red16[8 + warp] = s;
        __syncthreads();
        s = red16[8];
#pragma unroll
        for (int w = 1; w < 8; w++) s += red16[8 + w];
        inv[r] = 1.f / s;
    }
    __syncthreads();

    const int col = t & 127, h = t >> 7;
    float acc[RPB];
#pragma unroll
    for (int r = 0; r < RPB; r++) acc[r] = 0.f;
    const int jb = h * 512;
#pragma unroll 8
    for (int j = jb; j < jb + 512; j++) {
        float ev = embs[j * E + col];
#pragma unroll
        for (int r = 0; r < RPB; r++) acc[r] = fmaf(attn[r][j], ev, acc[r]);
    }
    if (h == 1) {
#pragma unroll
        for (int r = 0; r < RPB; r++) partial[r][col] = acc[r];
    }
    __syncthreads();
    if (h == 0) {
#pragma unroll
        for (int r = 0; r < RPB; r++) {
            int i = i0 + r;
            out[(size_t)i * (2 * E) + col] = embs[i * E + col];
            out[(size_t)i * (2 * E) + E + col] = (acc[r] + partial[r][col]) * inv[r];
        }
    }
}

// ---------------- launch ----------------
extern "C" void kernel_launch(void* const* d_in, const int* in_sizes, int n_in,
                              void* d_out, int out_size) {
    const float* embs = (const float*)d_in[0];
    const int*   adj  = (const int*)d_in[1];
    const float* pde  = (const float*)d_in[2];
    const float* W    = (const float*)d_in[3];
    const float* pcW  = (const float*)d_in[4];
    const float* pcb  = (const float*)d_in[5];
    const float* aW   = (const float*)d_in[6];
    const float* ab   = (const float*)d_in[7];
    float* out = (float*)d_out;

    cudaFuncSetAttribute(k_big, cudaFuncAttributeMaxDynamicSharedMemorySize,
                         (int)SMEM_DYN);
    cudaFuncSetAttribute(k_pre, cudaFuncAttributeMaxDynamicSharedMemorySize,
                         (int)PRE_SMEM);

    k_pre<<<N / IB, 128, PRE_SMEM>>>(embs, W, pcW, pcb, aW);      // launch 0
    k_wa2<<<1, E>>>(W, aW);                                       // launch 1
    k_bh<<<E, E>>>(pcW);                                          // launch 2
    k_big<<<dim3(N / BMJ, N / I_PER_CTA), 256, SMEM_DYN>>>(pde, adj, ab);  // launch 3
    k_out<<<N / RPB, 256>>>(embs, out);                           // launch 4
}

// round 15
// speedup vs baseline: 1.5342x; 1.1873x over previous
#include <cuda_runtime.h>
#include <cuda_fp16.h>
#include <math.h>
#include <cstdint>

#define N 1024
#define E 128
#define NEG 0.2f

#define I_PER_CTA 8
#define BMJ 128
#define LDH 136                   // half stride (272 B rows)
#define TILE_B (BMJ * LDH * 2)    // 34816
#define OFF_A0 0
#define OFF_A1 34816
#define OFF_B  69632
#define OFF_RS 104448             // rsum: 2 buffers x 128 x 2 floats
#define SMEM_DYN (OFF_RS + 2048)

// ---- scratch ----
__device__ float g_base[N * E];
__device__ float g_s[N];
__device__ float g_wa2[E];
__device__ float g_logits[(size_t)N * N];
__device__ __half g_Bh[E * E];   // pc_Wp fp16, [k][n]

__device__ __forceinline__ float lrelu(float x) { return fmaxf(x, NEG * x); }

__device__ __forceinline__ uint32_t smem_u32(const void* p) {
    return (uint32_t)__cvta_generic_to_shared(p);
}
__device__ __forceinline__ void ldsm_x4(uint32_t* r, uint32_t addr) {
    asm volatile("ldmatrix.sync.aligned.m8n8.x4.shared.b16 {%0,%1,%2,%3}, [%4];"
                 : "=r"(r[0]), "=r"(r[1]), "=r"(r[2]), "=r"(r[3]) : "r"(addr));
}
__device__ __forceinline__ void ldsm_x4_t(uint32_t* r, uint32_t addr) {
    asm volatile("ldmatrix.sync.aligned.m8n8.x4.trans.shared.b16 {%0,%1,%2,%3}, [%4];"
                 : "=r"(r[0]), "=r"(r[1]), "=r"(r[2]), "=r"(r[3]) : "r"(addr));
}
__device__ __forceinline__ void mma_h(uint32_t& d0, uint32_t& d1,
                                      const uint32_t* a, uint32_t b0, uint32_t b1) {
    asm volatile("mma.sync.aligned.m16n8k16.row.col.f16.f16.f16.f16 "
                 "{%0,%1},{%2,%3,%4,%5},{%6,%7},{%0,%1};"
                 : "+r"(d0), "+r"(d1)
                 : "r"(a[0]), "r"(a[1]), "r"(a[2]), "r"(a[3]), "r"(b0), "r"(b1));
}
__device__ __forceinline__ void mma_hf(float* d, const uint32_t* a, uint32_t b0, uint32_t b1) {
    asm volatile("mma.sync.aligned.m16n8k16.row.col.f32.f16.f16.f32 "
                 "{%0,%1,%2,%3},{%4,%5,%6,%7},{%8,%9},{%0,%1,%2,%3};"
                 : "+f"(d[0]), "+f"(d[1]), "+f"(d[2]), "+f"(d[3])
                 : "r"(a[0]), "r"(a[1]), "r"(a[2]), "r"(a[3]), "r"(b0), "r"(b1));
}
__device__ __forceinline__ uint32_t h2bits(__half2 v) { return *(uint32_t*)&v; }

// ---------------- k_pre: 8 rows/block, W/pcW staged through smem ----------------
#define IB 8
#define PRE_SMEM ((16384 + 2 * IB * 128 + 64) * 4)
__global__ void __launch_bounds__(128)
k_pre(const float* __restrict__ embs, const float* __restrict__ W,
      const float* __restrict__ pcW, const float* __restrict__ pcb,
      const float* __restrict__ aW) {
    extern __shared__ float ps[];
    float* Wsm = ps;
    float* es = ps + 16384;
    float* ws = es + IB * 128;
    float* scr = ws + IB * 128;
    const int l = threadIdx.x;
    const int warp = l >> 5, lane = l & 31;
    const int i0 = blockIdx.x * IB;

#pragma unroll
    for (int t = 0; t < 32; t++)
        ((float4*)Wsm)[l + t * 128] = ((const float4*)W)[l + t * 128];
#pragma unroll
    for (int r = 0; r < IB; r++) es[r * 128 + l] = embs[(i0 + r) * 128 + l];
    __syncthreads();

    float acc[IB];
#pragma unroll
    for (int r = 0; r < IB; r++) acc[r] = 0.f;
    for (int k = 0; k < 128; k++) {
        float wv = Wsm[k * 128 + l];
#pragma unroll
        for (int r = 0; r < IB; r++) acc[r] = fmaf(es[r * 128 + k], wv, acc[r]);
    }
#pragma unroll
    for (int r = 0; r < IB; r++) ws[r * 128 + l] = acc[r];

    float a1 = aW[l];
#pragma unroll
    for (int r = 0; r < IB; r++) {
        float v = acc[r] * a1;
#pragma unroll
        for (int off = 16; off > 0; off >>= 1) v += __shfl_xor_sync(0xffffffffu, v, off);
        if (lane == 0) scr[r * 4 + warp] = v;
    }
    __syncthreads();
    if (l < IB)
        g_s[i0 + l] = scr[l * 4] + scr[l * 4 + 1] + scr[l * 4 + 2] + scr[l * 4 + 3];
    __syncthreads();

#pragma unroll
    for (int t = 0; t < 32; t++)
        ((float4*)Wsm)[l + t * 128] = ((const float4*)pcW)[l + t * 128];
    __syncthreads();

    float b[IB];
    float bias = pcb[l];
#pragma unroll
    for (int r = 0; r < IB; r++) b[r] = bias;
    for (int k = 0; k < 128; k++) {
        float wv = Wsm[k * 128 + l];
#pragma unroll
        for (int r = 0; r < IB; r++) b[r] = fmaf(ws[r * 128 + k], wv, b[r]);
    }
#pragma unroll
    for (int r = 0; r < IB; r++) g_base[(size_t)(i0 + r) * 128 + l] = b[r];
}

__global__ void k_wa2(const float* __restrict__ W, const float* __restrict__ aW) {
    __shared__ float a2s[E];
    int m = threadIdx.x;
    a2s[m] = aW[E + m];
    __syncthreads();
    float acc = 0.f;
#pragma unroll 8
    for (int k = 0; k < E; k++) acc = fmaf(W[m * E + k], a2s[k], acc);
    g_wa2[m] = acc;
}

__global__ void k_bh(const float* __restrict__ pcW) {
    int idx = blockIdx.x * 128 + threadIdx.x;
    g_Bh[idx] = __float2half(pcW[E * E + idx]);
}

// ---------------- big kernel: raw mma, pipelined copy, 1 barrier/iter ----------------
__global__ void __launch_bounds__(256, 2)
k_big(const float* __restrict__ pde, const int* __restrict__ adj,
      const float* __restrict__ ab_ptr) {
    extern __shared__ char sm[];
    const uint32_t sb = smem_u32(sm);

    const int tid = threadIdx.x;
    const int lane = tid & 31;
    const int wid = tid >> 5;
    const int grp = lane >> 2, tig = lane & 3;
    const int lrow = lane & 15, lcb = (lane >> 4) * 8;
    const int j0 = blockIdx.x * BMJ;
    const int i_base = blockIdx.y * I_PER_CTA;
    const float ab = ab_ptr[0];
    const __half2 slope = __float2half2_rn(NEG);

    const int wr = (wid & 3) * 32;
    const int wcg = wid >> 2;
    const int wc = wcg * 64;

    // ---- prologue 1: base -> fp16 into A0 region ----
#pragma unroll
    for (int t = 0; t < 8; t++) {
        int idx = tid + t * 256;
        int row = idx >> 4, c8 = (idx & 15) * 8;
        const float4* g = (const float4*)(g_base + (size_t)(j0 + row) * E + c8);
        float4 v0 = g[0], v1 = g[1];
        __half2 p0 = __floats2half2_rn(v0.x, v0.y);
        __half2 p1 = __floats2half2_rn(v0.z, v0.w);
        __half2 p2 = __floats2half2_rn(v1.x, v1.y);
        __half2 p3 = __floats2half2_rn(v1.z, v1.w);
        uint4 o;
        o.x = h2bits(p0); o.y = h2bits(p1); o.z = h2bits(p2); o.w = h2bits(p3);
        *(uint4*)(sm + OFF_A0 + (row * LDH + c8) * 2) = o;
    }
    __syncthreads();

    uint32_t bf0[2][8], bf1[2][8];
#pragma unroll
    for (int rb = 0; rb < 2; rb++)
#pragma unroll
        for (int q = 0; q < 4; q++) {
            uint32_t r[4];
            ldsm_x4(r, sb + OFF_A0 + ((wr + 16 * rb + lrow) * LDH + wc + 16 * q + lcb) * 2);
            bf0[rb][2 * q] = r[0]; bf1[rb][2 * q] = r[1];
            bf0[rb][2 * q + 1] = r[2]; bf1[rb][2 * q + 1] = r[3];
        }
    uint32_t w2lo[4], w2hi[4];
#pragma unroll
    for (int kb = 0; kb < 4; kb++) {
        if (grp == 0) {
            int k0 = wc + 16 * kb + 2 * tig;
            w2lo[kb] = h2bits(__floats2half2_rn(g_wa2[k0], g_wa2[k0 + 1]));
            w2hi[kb] = h2bits(__floats2half2_rn(g_wa2[k0 + 8], g_wa2[k0 + 9]));
        } else { w2lo[kb] = 0; w2hi[kb] = 0; }
    }
    __syncthreads();

    // ---- prologue 2: B tile + A tile 0 ----
#pragma unroll
    for (int t = 0; t < 8; t++) {
        int idx = tid + t * 256;
        int row = idx >> 4, c8 = (idx & 15) * 8;
        *(uint4*)(sm + OFF_B + (row * LDH + c8) * 2) = *(const uint4*)(g_Bh + row * E + c8);
    }
    {
        const float* gA = pde + ((size_t)i_base * N + j0) * E;
#pragma unroll
        for (int t = 0; t < 8; t++) {
            int idx = tid + t * 256;
            int row = idx >> 4, c8 = (idx & 15) * 8;
            const float4* g = (const float4*)(gA + (size_t)row * E + c8);
            float4 v0 = g[0], v1 = g[1];
            __half2 p0 = __floats2half2_rn(v0.x, v0.y);
            __half2 p1 = __floats2half2_rn(v0.z, v0.w);
            __half2 p2 = __floats2half2_rn(v1.x, v1.y);
            __half2 p3 = __floats2half2_rn(v1.z, v1.w);
            uint4 o;
            o.x = h2bits(p0); o.y = h2bits(p1); o.z = h2bits(p2); o.w = h2bits(p3);
            *(uint4*)(sm + OFF_A0 + (row * LDH + c8) * 2) = o;
        }
    }
    __syncthreads();

    const uint32_t bB = sb + OFF_B;

    for (int s = 0; s < I_PER_CTA; s++) {
        const uint32_t bA = sb + ((s & 1) ? OFF_A1 : OFF_A0);
        char* dst = sm + ((s & 1) ? OFF_A0 : OFF_A1);
        const int i = i_base + s;
        const bool do_copy = (s + 1 < I_PER_CTA);
        const float* gA = pde + ((size_t)(i_base + s + 1) * N + j0) * E;

        uint32_t fc0[2][8], fc1[2][8];
#pragma unroll
        for (int rb = 0; rb < 2; rb++)
#pragma unroll
            for (int cb = 0; cb < 8; cb++) { fc0[rb][cb] = 0; fc1[rb][cb] = 0; }

        // ---- pipelined: 4 copy-batches interleaved with 2 mma k-steps each ----
#pragma unroll
        for (int bq = 0; bq < 4; bq++) {
            float4 st[4];
            if (do_copy) {
#pragma unroll
                for (int u = 0; u < 2; u++) {
                    int t = bq * 2 + u;
                    int idx = tid + t * 256;
                    int row = idx >> 4, c8 = (idx & 15) * 8;
                    const float4* g = (const float4*)(gA + (size_t)row * E + c8);
                    st[2 * u] = g[0];
                    st[2 * u + 1] = g[1];
                }
            }
#pragma unroll
            for (int kk = 0; kk < 2; kk++) {
                const int ks = bq * 2 + kk;
                uint32_t a[2][4];
                ldsm_x4(a[0], bA + ((wr + lrow) * LDH + ks * 16 + lcb) * 2);
                ldsm_x4(a[1], bA + ((wr + 16 + lrow) * LDH + ks * 16 + lcb) * 2);
#pragma unroll
                for (int q = 0; q < 4; q++) {
                    uint32_t b[4];
                    ldsm_x4_t(b, bB + ((ks * 16 + lrow) * LDH + wc + 16 * q + lcb) * 2);
#pragma unroll
                    for (int rb = 0; rb < 2; rb++) {
                        mma_h(fc0[rb][2 * q], fc1[rb][2 * q], a[rb], b[0], b[1]);
                        mma_h(fc0[rb][2 * q + 1], fc1[rb][2 * q + 1], a[rb], b[2], b[3]);
                    }
                }
            }
            if (do_copy) {
#pragma unroll
                for (int u = 0; u < 2; u++) {
                    int t = bq * 2 + u;
                    int idx = tid + t * 256;
                    int row = idx >> 4, c8 = (idx & 15) * 8;
                    float4 v0 = st[2 * u], v1 = st[2 * u + 1];
                    __half2 p0 = __floats2half2_rn(v0.x, v0.y);
                    __half2 p1 = __floats2half2_rn(v0.z, v0.w);
                    __half2 p2 = __floats2half2_rn(v1.x, v1.y);
                    __half2 p3 = __floats2half2_rn(v1.z, v1.w);
                    uint4 o;
                    o.x = h2bits(p0); o.y = h2bits(p1); o.z = h2bits(p2); o.w = h2bits(p3);
                    *(uint4*)(dst + (row * LDH + c8) * 2) = o;
                }
            }
        }

        // ---- P = lrelu(fc + base), in registers ----
#pragma unroll
        for (int rb = 0; rb < 2; rb++)
#pragma unroll
            for (int cb = 0; cb < 8; cb++) {
                __half2 v0 = __hadd2(*(__half2*)&fc0[rb][cb], *(__half2*)&bf0[rb][cb]);
                __half2 v1 = __hadd2(*(__half2*)&fc1[rb][cb], *(__half2*)&bf1[rb][cb]);
                *(__half2*)&fc0[rb][cb] = __hmax2(v0, __hmul2(v0, slope));
                *(__half2*)&fc1[rb][cb] = __hmax2(v1, __hmul2(v1, slope));
            }

        // ---- reduction mma, double-buffered rsum ----
        float* rsum = (float*)(sm + OFF_RS + (s & 1) * 1024);
        float racc[2][4];
#pragma unroll
        for (int rb = 0; rb < 2; rb++) {
#pragma unroll
            for (int e = 0; e < 4; e++) racc[rb][e] = 0.f;
#pragma unroll
            for (int kb = 0; kb < 4; kb++) {
                uint32_t aop[4] = { fc0[rb][2 * kb], fc1[rb][2 * kb],
                                    fc0[rb][2 * kb + 1], fc1[rb][2 * kb + 1] };
                mma_hf(racc[rb], aop, w2lo[kb], w2hi[kb]);
            }
            if (tig == 0) {
                rsum[(wr + 16 * rb + grp) * 2 + wcg] = racc[rb][0];
                rsum[(wr + 16 * rb + 8 + grp) * 2 + wcg] = racc[rb][2];
            }
        }
        __syncthreads();   // rsum visible; A[s] ldsm done; A[s+1] STS done

        if (tid < 128) {
            float part = rsum[2 * tid] + rsum[2 * tid + 1];
            float lg = lrelu(g_s[i] + part + ab);
            size_t oidx = (size_t)i * N + j0 + tid;
            g_logits[oidx] = (adj[oidx] == 1) ? lg : -1e30f;
        }
        // no second barrier: next iter writes the OTHER rsum buffer; A-buffer WAR
        // is covered by the sync above (all ldsm reads of A[s] precede it).
    }
}

// ---------------- softmax + attn@embs + concat (512 blocks) ----------------
#define RPB 2
__global__ void __launch_bounds__(256)
k_out(const float* __restrict__ embs, float* __restrict__ out) {
    __shared__ float attn[RPB][N];
    __shared__ float red16[16];
    __shared__ float partial[RPB][E];
    const int i0 = blockIdx.x * RPB;
    const int t = threadIdx.x;
    const int warp = t >> 5, lane = t & 31;

    float inv[RPB];
#pragma unroll
    for (int r = 0; r < RPB; r++) {
        const float* lg = g_logits + (size_t)(i0 + r) * N;
        float v0 = lg[t], v1 = lg[t + 256], v2 = lg[t + 512], v3 = lg[t + 768];
        float m = fmaxf(fmaxf(v0, v1), fmaxf(v2, v3));
#pragma unroll
        for (int off = 16; off > 0; off >>= 1)
            m = fmaxf(m, __shfl_xor_sync(0xffffffffu, m, off));
        if (lane == 0) red16[warp] = m;
        __syncthreads();
        m = red16[0];
#pragma unroll
        for (int w = 1; w < 8; w++) m = fmaxf(m, red16[w]);

        float e0 = expf(v0 - m), e1 = expf(v1 - m), e2 = expf(v2 - m), e3 = expf(v3 - m);
        attn[r][t] = e0; attn[r][t + 256] = e1; attn[r][t + 512] = e2; attn[r][t + 768] = e3;
        float s = e0 + e1 + e2 + e3;
#pragma unroll
        for (int off = 16; off > 0; off >>= 1)
            s += __shfl_xor_sync(0xffffffffu, s, off);
        if (lane == 0) red16[8 + warp] = s;
        __syncthreads();
        s = red16[8];
#pragma unroll
        for (int w = 1; w < 8; w++) s += red16[8 + w];
        inv[r] = 1.f / s;
    }
    __syncthreads();

    const int col = t & 127, h = t >> 7;
    float acc[RPB];
#pragma unroll
    for (int r = 0; r < RPB; r++) acc[r] = 0.f;
    const int jb = h * 512;
#pragma unroll 8
    for (int j = jb; j < jb + 512; j++) {
        float ev = embs[j * E + col];
#pragma unroll
        for (int r = 0; r < RPB; r++) acc[r] = fmaf(attn[r][j], ev, acc[r]);
    }
    if (h == 1) {
#pragma unroll
        for (int r = 0; r < RPB; r++) partial[r][col] = acc[r];
    }
    __syncthreads();
    if (h == 0) {
#pragma unroll
        for (int r = 0; r < RPB; r++) {
            int i = i0 + r;
            out[(size_t)i * (2 * E) + col] = embs[i * E + col];
            out[(size_t)i * (2 * E) + E + col] = (acc[r] + partial[r][col]) * inv[r];
        }
    }
}

// ---------------- launch ----------------
extern "C" void kernel_launch(void* const* d_in, const int* in_sizes, int n_in,
                              void* d_out, int out_size) {
    const float* embs = (const float*)d_in[0];
    const int*   adj  = (const int*)d_in[1];
    const float* pde  = (const float*)d_in[2];
    const float* W    = (const float*)d_in[3];
    const float* pcW  = (const float*)d_in[4];
    const float* pcb  = (const float*)d_in[5];
    const float* aW   = (const float*)d_in[6];
    const float* ab   = (const float*)d_in[7];
    float* out = (float*)d_out;

    cudaFuncSetAttribute(k_big, cudaFuncAttributeMaxDynamicSharedMemorySize,
                         (int)SMEM_DYN);
    cudaFuncSetAttribute(k_pre, cudaFuncAttributeMaxDynamicSharedMemorySize,
                         (int)PRE_SMEM);

    k_pre<<<N / IB, 128, PRE_SMEM>>>(embs, W, pcW, pcb, aW);      // launch 0
    k_wa2<<<1, E>>>(W, aW);                                       // launch 1
    k_bh<<<E, E>>>(pcW);                                          // launch 2
    k_big<<<dim3(N / BMJ, N / I_PER_CTA), 256, SMEM_DYN>>>(pde, adj, ab);  // launch 3
    k_out<<<N / RPB, 256>>>(embs, out);                           // launch 4
}